// round 1
// baseline (speedup 1.0000x reference)
#include <cuda_runtime.h>
#include <math.h>

// Problem constants (fixed by setup_inputs)
#define DDIM 1024
#define NCLS 64

// Scratch: class-aggregated normalized support vectors, W[c][d]
__device__ float g_W[NCLS * DDIM];

// ---------------------------------------------------------------------------
// Kernel 0: zero W (must run every launch — graph replays)
// ---------------------------------------------------------------------------
__global__ void zeroW_kernel() {
    int i = blockIdx.x * blockDim.x + threadIdx.x;
    if (i < NCLS * DDIM) g_W[i] = 0.0f;
}

// ---------------------------------------------------------------------------
// Kernel 1: scatter. One block (128 threads) per support row n:
//   rinv = 1/||gS[n]||;  atomicAdd W[target[n]][d] += gS[n][d] * rinv
// ---------------------------------------------------------------------------
__global__ __launch_bounds__(128) void scatter_kernel(
    const float* __restrict__ gS, const void* __restrict__ tgt_raw) {

    const int n = blockIdx.x;
    const int t = threadIdx.x;

    // Detect int64 vs int32 labels: if int64 (little-endian, values 0..63),
    // every odd 32-bit word of the first 64 elements is 0. For int32 random
    // labels the probability of that is (1/64)^64 ~ 0.
    __shared__ int s_is64;
    if (t == 0) {
        const int* p = (const int*)tgt_raw;
        int acc = 0;
        #pragma unroll 4
        for (int i = 1; i < 128; i += 2) acc |= p[i];
        s_is64 = (acc == 0);
    }

    const float4* row = reinterpret_cast<const float4*>(gS + (size_t)n * DDIM);
    float4 v0 = row[t];          // elems 4t .. 4t+3
    float4 v1 = row[t + 128];    // elems 4(t+128) .. +3

    float ss = v0.x*v0.x + v0.y*v0.y + v0.z*v0.z + v0.w*v0.w
             + v1.x*v1.x + v1.y*v1.y + v1.z*v1.z + v1.w*v1.w;
    #pragma unroll
    for (int o = 16; o > 0; o >>= 1) ss += __shfl_xor_sync(0xffffffffu, ss, o);

    __shared__ float s_ws[4];
    if ((t & 31) == 0) s_ws[t >> 5] = ss;
    __syncthreads();
    const float rinv = rsqrtf(s_ws[0] + s_ws[1] + s_ws[2] + s_ws[3]);

    int c;
    if (s_is64) c = (int)((const long long*)tgt_raw)[n];
    else        c = ((const int*)tgt_raw)[n];
    c &= (NCLS - 1);  // safety clamp (NCLS is a power of 2)

    float* __restrict__ w = g_W + (size_t)c * DDIM;
    const int e0 = t * 4;
    const int e1 = (t + 128) * 4;
    atomicAdd(w + e0 + 0, v0.x * rinv);
    atomicAdd(w + e0 + 1, v0.y * rinv);
    atomicAdd(w + e0 + 2, v0.z * rinv);
    atomicAdd(w + e0 + 3, v0.w * rinv);
    atomicAdd(w + e1 + 0, v1.x * rinv);
    atomicAdd(w + e1 + 1, v1.y * rinv);
    atomicAdd(w + e1 + 2, v1.z * rinv);
    atomicAdd(w + e1 + 3, v1.w * rinv);
}

// ---------------------------------------------------------------------------
// Kernel 2: out[m][c] = (fX[m] . W[c]) * rsqrt(||fX[m]||^2)
// Tile: 64 rows (m) x 64 cols (c) per block, 256 threads, 4x4 microtile,
// TK=16. fX-row sumsq fused into the A-tile loads (each loader thread stays
// on a fixed row), so fX is read exactly once from HBM.
// ---------------------------------------------------------------------------
__global__ __launch_bounds__(256) void gemm_kernel(
    const float* __restrict__ fX, float* __restrict__ out) {

    __shared__ __align__(16) float As[16][64];  // [k][m]
    __shared__ __align__(16) float Bs[16][64];  // [k][c]
    __shared__ float s_pn[256];
    __shared__ float s_finv[64];

    const int t  = threadIdx.x;
    const int m0 = blockIdx.x * 64;

    // loader mapping: row r (0..63), quad q (0..3) -> 4 consecutive k-cols
    const int r = t >> 2;
    const int q = t & 3;
    // compute mapping: 4x4 microtile
    const int tm0 = (t >> 4) * 4;   // row group 0..60
    const int tc0 = (t & 15) * 4;   // col group 0..60

    const float* aptr = fX  + (size_t)(m0 + r) * DDIM + q * 4;
    const float* bptr = g_W + (size_t)r        * DDIM + q * 4;

    float4 apre = *(const float4*)(aptr);
    float4 bpre = *(const float4*)(bptr);

    float acc[4][4] = {};
    float ssq = 0.0f;

    for (int kk = 0; kk < DDIM; kk += 16) {
        // commit prefetched tile to shared
        As[q*4+0][r] = apre.x; As[q*4+1][r] = apre.y;
        As[q*4+2][r] = apre.z; As[q*4+3][r] = apre.w;
        Bs[q*4+0][r] = bpre.x; Bs[q*4+1][r] = bpre.y;
        Bs[q*4+2][r] = bpre.z; Bs[q*4+3][r] = bpre.w;
        ssq += apre.x*apre.x + apre.y*apre.y + apre.z*apre.z + apre.w*apre.w;
        __syncthreads();

        // issue next tile's global loads early — hidden under compute
        if (kk + 16 < DDIM) {
            apre = *(const float4*)(aptr + kk + 16);
            bpre = *(const float4*)(bptr + kk + 16);
        }

        #pragma unroll
        for (int k = 0; k < 16; ++k) {
            const float4 av = *(const float4*)(&As[k][tm0]);
            const float4 bv = *(const float4*)(&Bs[k][tc0]);
            const float a0 = av.x, a1 = av.y, a2 = av.z, a3 = av.w;
            const float b0 = bv.x, b1 = bv.y, b2 = bv.z, b3 = bv.w;
            acc[0][0] += a0*b0; acc[0][1] += a0*b1; acc[0][2] += a0*b2; acc[0][3] += a0*b3;
            acc[1][0] += a1*b0; acc[1][1] += a1*b1; acc[1][2] += a1*b2; acc[1][3] += a1*b3;
            acc[2][0] += a2*b0; acc[2][1] += a2*b1; acc[2][2] += a2*b2; acc[2][3] += a2*b3;
            acc[3][0] += a3*b0; acc[3][1] += a3*b1; acc[3][2] += a3*b2; acc[3][3] += a3*b3;
        }
        __syncthreads();
    }

    // reduce per-row sumsq -> finv (4 loader threads per row)
    s_pn[t] = ssq;
    __syncthreads();
    if (t < 64) {
        const float s = s_pn[t*4] + s_pn[t*4+1] + s_pn[t*4+2] + s_pn[t*4+3];
        s_finv[t] = rsqrtf(s);
    }
    __syncthreads();

    #pragma unroll
    for (int i = 0; i < 4; ++i) {
        const float fi = s_finv[tm0 + i];
        float4 o;
        o.x = acc[i][0] * fi;
        o.y = acc[i][1] * fi;
        o.z = acc[i][2] * fi;
        o.w = acc[i][3] * fi;
        *(float4*)(&out[(size_t)(m0 + tm0 + i) * NCLS + tc0]) = o;
    }
}

// ---------------------------------------------------------------------------
// Launch
// inputs (metadata order): gS [N,1024] f32, fX [M,1024] f32,
//                          trainTarget [N] int64/int32, nClasses (unused)
// output: [M, 64] f32
// ---------------------------------------------------------------------------
extern "C" void kernel_launch(void* const* d_in, const int* in_sizes, int n_in,
                              void* d_out, int out_size) {
    const float* gS = (const float*)d_in[0];
    const float* fX = (const float*)d_in[1];
    const void*  tg = d_in[2];

    const int N = in_sizes[0] / DDIM;   // 4096
    const int M = in_sizes[1] / DDIM;   // 8192

    zeroW_kernel<<<(NCLS * DDIM + 255) / 256, 256>>>();
    scatter_kernel<<<N, 128>>>(gS, tg);
    gemm_kernel<<<M / 64, 256>>>(fX, (float*)d_out);
}

// round 2
// speedup vs baseline: 1.1715x; 1.1715x over previous
#include <cuda_runtime.h>
#include <math.h>

#define DDIM 1024
#define NCLS 64
#define NSUP 4096

// Scratch (device globals — no allocation allowed)
__device__ float g_W[NCLS * DDIM];     // class-aggregated normalized supports
__device__ float g_rinv[NSUP];         // 1/||gS[n]||

typedef unsigned long long ull;

// packed f32x2 FMA: d = a*b + d (elementwise on 2-vector)
#define FFMA2(d, a, b) asm("fma.rn.f32x2 %0, %1, %2, %0;" : "+l"(d) : "l"(a), "l"(b))

union F2U { ull u; float2 f; };

// ---------------------------------------------------------------------------
// Kernel 1: rinv[n] = rsqrt(||gS[n]||^2). One warp per row, 8 rows per block.
// ---------------------------------------------------------------------------
__global__ __launch_bounds__(256) void norms_kernel(const float* __restrict__ gS) {
    const int n    = blockIdx.x * 8 + (threadIdx.x >> 5);
    const int lane = threadIdx.x & 31;
    const float4* row = reinterpret_cast<const float4*>(gS + (size_t)n * DDIM);
    float ss = 0.0f;
    #pragma unroll
    for (int i = 0; i < 8; ++i) {
        float4 v = row[lane + 32 * i];
        ss += v.x*v.x + v.y*v.y + v.z*v.z + v.w*v.w;
    }
    #pragma unroll
    for (int o = 16; o > 0; o >>= 1) ss += __shfl_xor_sync(0xffffffffu, ss, o);
    if (lane == 0) g_rinv[n] = rsqrtf(ss);
}

// ---------------------------------------------------------------------------
// Kernel 2: gather. Block (c, slice) sums gS[n][slice]*rinv[n] over all n with
// label c, in ascending n order (deterministic), writes W[c][slice]. No atomics.
// ---------------------------------------------------------------------------
__global__ __launch_bounds__(256) void gather_kernel(
    const float* __restrict__ gS, const void* __restrict__ tgt_raw, int N) {

    const int c  = blockIdx.x >> 2;
    const int sl = blockIdx.x & 3;          // 256-float d-slice
    const int t  = threadIdx.x;
    const int warp = t >> 5, lane = t & 31;

    __shared__ int   s_is64;
    __shared__ short s_stage[8][128];
    __shared__ int   s_wcnt[8];
    __shared__ int   s_off[9];
    __shared__ short s_rows[512];

    const int* tgt32 = (const int*)tgt_raw;
    if (t == 0) {
        int acc = 0;
        #pragma unroll 4
        for (int i = 1; i < 128; i += 2) acc |= tgt32[i];  // int64 labels => odd words 0
        s_is64 = (acc == 0);
    }
    __syncthreads();
    const int is64 = s_is64;

    // phase 1: per-warp ordered match lists over segment [warp*N/8, ...)
    const int seg = N >> 3;
    const int base = warp * seg;
    int cnt = 0;
    for (int ch = 0; ch < seg; ch += 32) {
        const int n = base + ch + lane;
        const int lbl = is64 ? tgt32[2 * n] : tgt32[n];
        const bool m = (lbl == c);
        const unsigned msk = __ballot_sync(0xffffffffu, m);
        if (m) {
            int pos = cnt + __popc(msk & ((1u << lane) - 1u));
            if (pos < 128) s_stage[warp][pos] = (short)n;
        }
        cnt += __popc(msk);
    }
    if (cnt > 128) cnt = 128;
    if (lane == 0) s_wcnt[warp] = cnt;
    __syncthreads();
    if (t == 0) {
        int o = 0;
        #pragma unroll
        for (int w = 0; w < 8; ++w) { s_off[w] = o; o += s_wcnt[w]; }
        s_off[8] = o;
    }
    __syncthreads();
    for (int i = lane; i < s_wcnt[warp]; i += 32)
        s_rows[s_off[warp] + i] = s_stage[warp][i];
    __syncthreads();
    const int total = s_off[8];

    // phase 2: ordered sum over matching rows (gS is L2-resident after norms)
    const float* gsl = gS + sl * 256 + t;
    float a0 = 0.0f, a1 = 0.0f;
    int r = 0;
    for (; r + 2 <= total; r += 2) {
        const int n0 = s_rows[r], n1 = s_rows[r + 1];
        const float v0 = gsl[(size_t)n0 * DDIM];
        const float v1 = gsl[(size_t)n1 * DDIM];
        a0 += v0 * g_rinv[n0];
        a1 += v1 * g_rinv[n1];
    }
    if (r < total) {
        const int n0 = s_rows[r];
        a0 += gsl[(size_t)n0 * DDIM] * g_rinv[n0];
    }
    g_W[c * DDIM + sl * 256 + t] = a0 + a1;
}

// ---------------------------------------------------------------------------
// Kernel 3: out[m][c] = (fX[m].W[c]) * rsqrt(||fX[m]||^2)
// 64x64 tile, 256 threads. Packed f32x2 FMA over k-parity:
//   acc2 = {sum over even k, sum over odd k}; final = lo+hi.
// Smem k-contiguous (stride 18 floats -> 16 distinct banks for both operand
// access patterns). Per-thread microtile 4m x 4c.
// ---------------------------------------------------------------------------
__global__ __launch_bounds__(256) void gemm_kernel(
    const float* __restrict__ fX, float* __restrict__ out) {

    __shared__ __align__(16) float As[64][18];  // [m][k] within tile
    __shared__ __align__(16) float Bs[64][18];  // [c][k] within tile
    __shared__ float s_pn[256];
    __shared__ float s_finv[64];

    const int t  = threadIdx.x;
    const int m0 = blockIdx.x * 64;

    // loader mapping: row r (m or c index 0..63), quad q -> 4 consecutive k
    const int r = t >> 2;
    const int q = t & 3;
    // compute mapping: mg -> 4 consecutive m rows; cg -> 4 strided c cols
    const int mg = t >> 4;        // 0..15
    const int cg = t & 15;        // 0..15; c set {cg, cg+16, cg+32, cg+48}

    const float* aptr = fX  + (size_t)(m0 + r) * DDIM + q * 4;
    const float* bptr = g_W + (size_t)r        * DDIM + q * 4;

    float4 apre = *(const float4*)(aptr);
    float4 bpre = *(const float4*)(bptr);

    ull acc[4][4];
    #pragma unroll
    for (int i = 0; i < 4; ++i)
        #pragma unroll
        for (int j = 0; j < 4; ++j) acc[i][j] = 0ull;
    float ssq = 0.0f;

    for (int kk = 0; kk < DDIM; kk += 16) {
        As[r][q*4+0] = apre.x; As[r][q*4+1] = apre.y;
        As[r][q*4+2] = apre.z; As[r][q*4+3] = apre.w;
        Bs[r][q*4+0] = bpre.x; Bs[r][q*4+1] = bpre.y;
        Bs[r][q*4+2] = bpre.z; Bs[r][q*4+3] = bpre.w;
        ssq += apre.x*apre.x + apre.y*apre.y + apre.z*apre.z + apre.w*apre.w;
        __syncthreads();

        if (kk + 16 < DDIM) {
            apre = *(const float4*)(aptr + kk + 16);
            bpre = *(const float4*)(bptr + kk + 16);
        }

        #pragma unroll
        for (int kp = 0; kp < 8; ++kp) {   // k-pairs
            ull a2[4], b2[4];
            #pragma unroll
            for (int i = 0; i < 4; ++i)
                a2[i] = *reinterpret_cast<const ull*>(&As[4*mg + i][2*kp]);
            #pragma unroll
            for (int j = 0; j < 4; ++j)
                b2[j] = *reinterpret_cast<const ull*>(&Bs[cg + 16*j][2*kp]);
            #pragma unroll
            for (int i = 0; i < 4; ++i)
                #pragma unroll
                for (int j = 0; j < 4; ++j)
                    FFMA2(acc[i][j], a2[i], b2[j]);
        }
        __syncthreads();
    }

    // per-row 1/||fX|| from loader-fused partial sums
    s_pn[t] = ssq;
    __syncthreads();
    if (t < 64) {
        const float s = s_pn[t*4] + s_pn[t*4+1] + s_pn[t*4+2] + s_pn[t*4+3];
        s_finv[t] = rsqrtf(s);
    }
    __syncthreads();

    #pragma unroll
    for (int i = 0; i < 4; ++i) {
        const int   m  = 4*mg + i;
        const float fi = s_finv[m];
        #pragma unroll
        for (int j = 0; j < 4; ++j) {
            F2U u; u.u = acc[i][j];
            out[(size_t)(m0 + m) * NCLS + cg + 16*j] = (u.f.x + u.f.y) * fi;
        }
    }
}

// ---------------------------------------------------------------------------
// inputs: gS [N,1024] f32, fX [M,1024] f32, trainTarget [N] i64/i32, nClasses
// output: [M, 64] f32
// ---------------------------------------------------------------------------
extern "C" void kernel_launch(void* const* d_in, const int* in_sizes, int n_in,
                              void* d_out, int out_size) {
    const float* gS = (const float*)d_in[0];
    const float* fX = (const float*)d_in[1];
    const void*  tg = d_in[2];

    const int N = in_sizes[0] / DDIM;   // 4096
    const int M = in_sizes[1] / DDIM;   // 8192

    norms_kernel<<<N / 8, 256>>>(gS);
    gather_kernel<<<NCLS * 4, 256>>>(gS, tg, N);
    gemm_kernel<<<M / 64, 256>>>(fX, (float*)d_out);
}

// round 3
// speedup vs baseline: 1.2155x; 1.0375x over previous
#include <cuda_runtime.h>
#include <math.h>

#define DDIM 1024
#define NCLS 64
#define NSUP 4096
#define RCAP 192

// Scratch (device globals — no allocation allowed)
__device__ float g_W[NCLS * DDIM];     // class-aggregated normalized supports (tf32-rounded)
__device__ float g_rinv[NSUP];         // 1/||gS[n]||
__device__ int   g_rows[NCLS * RCAP];  // ordered row lists per class
__device__ int   g_cnt[NCLS];

__device__ __forceinline__ unsigned cvt_tf32(float f) {
    unsigned u;
    asm("cvt.rna.tf32.f32 %0, %1;" : "=r"(u) : "f"(f));
    return u;
}

__device__ __forceinline__ void mma_tf32(float* d, const unsigned* a,
                                         unsigned b0, unsigned b1) {
    asm volatile(
        "mma.sync.aligned.m16n8k8.row.col.f32.tf32.tf32.f32 "
        "{%0,%1,%2,%3}, {%4,%5,%6,%7}, {%8,%9}, {%0,%1,%2,%3};"
        : "+f"(d[0]), "+f"(d[1]), "+f"(d[2]), "+f"(d[3])
        : "r"(a[0]), "r"(a[1]), "r"(a[2]), "r"(a[3]), "r"(b0), "r"(b1));
}

// ---------------------------------------------------------------------------
// Kernel 1: rinv[n] = rsqrt(||gS[n]||^2). One warp per row.
// ---------------------------------------------------------------------------
__global__ __launch_bounds__(256) void norms_kernel(const float* __restrict__ gS) {
    const int n    = blockIdx.x * 8 + (threadIdx.x >> 5);
    const int lane = threadIdx.x & 31;
    const float4* row = reinterpret_cast<const float4*>(gS + (size_t)n * DDIM);
    float ss = 0.0f;
    #pragma unroll
    for (int i = 0; i < 8; ++i) {
        float4 v = row[lane + 32 * i];
        ss += v.x*v.x + v.y*v.y + v.z*v.z + v.w*v.w;
    }
    #pragma unroll
    for (int o = 16; o > 0; o >>= 1) ss += __shfl_xor_sync(0xffffffffu, ss, o);
    if (lane == 0) g_rinv[n] = rsqrtf(ss);
}

// ---------------------------------------------------------------------------
// Kernel 2: build ordered per-class row lists (once, shared by all gathers).
// One block per class; per-warp ballot compaction over disjoint segments,
// then ordered concatenation. Deterministic.
// ---------------------------------------------------------------------------
__global__ __launch_bounds__(256) void build_kernel(const void* __restrict__ tgt_raw,
                                                    int N) {
    const int c = blockIdx.x;
    const int t = threadIdx.x;
    const int warp = t >> 5, lane = t & 31;

    __shared__ int   s_is64;
    __shared__ short s_stage[8][64];
    __shared__ int   s_wcnt[8];
    __shared__ int   s_off[9];

    const int* tgt32 = (const int*)tgt_raw;
    if (t == 0) {
        int acc = 0;
        #pragma unroll 4
        for (int i = 1; i < 128; i += 2) acc |= tgt32[i];  // int64 => odd words 0
        s_is64 = (acc == 0);
    }
    __syncthreads();
    const int is64 = s_is64;

    const int seg = N >> 3;
    const int base = warp * seg;
    int cnt = 0;
    for (int ch = 0; ch < seg; ch += 32) {
        const int n = base + ch + lane;
        const int lbl = is64 ? tgt32[2 * n] : tgt32[n];
        const bool m = (lbl == c);
        const unsigned msk = __ballot_sync(0xffffffffu, m);
        if (m) {
            int pos = cnt + __popc(msk & ((1u << lane) - 1u));
            if (pos < 64) s_stage[warp][pos] = (short)n;
        }
        cnt += __popc(msk);
    }
    if (cnt > 64) cnt = 64;
    if (lane == 0) s_wcnt[warp] = cnt;
    __syncthreads();
    if (t == 0) {
        int o = 0;
        #pragma unroll
        for (int w = 0; w < 8; ++w) { s_off[w] = o; o += s_wcnt[w]; }
        s_off[8] = o;
        g_cnt[c] = (o < RCAP) ? o : RCAP;
    }
    __syncthreads();
    for (int i = lane; i < s_wcnt[warp]; i += 32) {
        const int pos = s_off[warp] + i;
        if (pos < RCAP) g_rows[c * RCAP + pos] = (int)s_stage[warp][i];
    }
}

// ---------------------------------------------------------------------------
// Kernel 3: gather. Block (c, slice of 128 d) sums gS[n][d]*rinv[n] over the
// ordered row list of class c (deterministic, no atomics; gS is L2-resident
// after norms). Output pre-rounded to tf32 for the tensor-core GEMM.
// ---------------------------------------------------------------------------
__global__ __launch_bounds__(128) void gather_kernel(const float* __restrict__ gS) {
    const int c  = blockIdx.x >> 3;
    const int sl = blockIdx.x & 7;
    const int t  = threadIdx.x;

    const int cnt = g_cnt[c];
    const int* rows = g_rows + c * RCAP;
    const float* gsl = gS + sl * 128 + t;

    float a0 = 0.f, a1 = 0.f, a2 = 0.f, a3 = 0.f;
    int r = 0;
    for (; r + 4 <= cnt; r += 4) {
        const int n0 = rows[r], n1 = rows[r+1], n2 = rows[r+2], n3 = rows[r+3];
        a0 += gsl[(size_t)n0 * DDIM] * g_rinv[n0];
        a1 += gsl[(size_t)n1 * DDIM] * g_rinv[n1];
        a2 += gsl[(size_t)n2 * DDIM] * g_rinv[n2];
        a3 += gsl[(size_t)n3 * DDIM] * g_rinv[n3];
    }
    for (; r < cnt; ++r) {
        const int n0 = rows[r];
        a0 += gsl[(size_t)n0 * DDIM] * g_rinv[n0];
    }
    const float v = (a0 + a1) + (a2 + a3);
    g_W[c * DDIM + sl * 128 + t] = __uint_as_float(cvt_tf32(v));
}

// ---------------------------------------------------------------------------
// Kernel 4: tensor-core GEMM. out[m][c] = (fX[m].W[c]) * rsqrt(||fX[m]||^2)
// mma.sync m16n8k8 tf32. Block: 128m x 64c, 4 warps (warp = 32m x 64c),
// K-chunk 16, double-buffered smem (pad 20 -> conflict-free fragment loads).
// fX ssq fused into the f32 load path (fX read exactly once); A converted
// to tf32 via cvt.rna on the smem-store path; B pre-rounded by gather.
// ---------------------------------------------------------------------------
__global__ __launch_bounds__(128) void gemm_kernel(
    const float* __restrict__ fX, float* __restrict__ out) {

    __shared__ __align__(16) float As[2][128 * 20];
    __shared__ __align__(16) float Bs[2][64 * 20];
    __shared__ float s_pn[4][32][4];
    __shared__ float s_finv[128];

    const int t    = threadIdx.x;
    const int warp = t >> 5;
    const int lane = t & 31;
    const int g    = lane >> 2;    // group id 0..7
    const int tid  = lane & 3;     // thread-in-group 0..3
    const int m0   = blockIdx.x * 128;

    // loader mapping: ar = row-within-32-chunk, ac = 4-float column offset
    const int ar = t >> 2;         // 0..31
    const int ac = (t & 3) * 4;    // 0,4,8,12

    const float* aG = fX  + (size_t)(m0 + ar) * DDIM + ac;
    const float* bG = g_W + (size_t)ar        * DDIM + ac;

    float acc[2][8][4];
    #pragma unroll
    for (int i = 0; i < 2; ++i)
        #pragma unroll
        for (int j = 0; j < 8; ++j)
            #pragma unroll
            for (int k = 0; k < 4; ++k) acc[i][j][k] = 0.0f;

    float ssq[4] = {0.f, 0.f, 0.f, 0.f};

    float4 aR[4], bR[2];
    #pragma unroll
    for (int p = 0; p < 4; ++p) aR[p] = *(const float4*)(aG + (size_t)(32 * p) * DDIM);
    bR[0] = *(const float4*)(bG);
    bR[1] = *(const float4*)(bG + (size_t)32 * DDIM);

    for (int kk = 0; kk < DDIM; kk += 16) {
        const int cur = (kk >> 4) & 1;

        // commit prefetched chunk: f32 ssq, then tf32 round, then STS.128
        #pragma unroll
        for (int p = 0; p < 4; ++p) {
            const float4 v = aR[p];
            ssq[p] += v.x*v.x + v.y*v.y + v.z*v.z + v.w*v.w;
            uint4 u;
            u.x = cvt_tf32(v.x); u.y = cvt_tf32(v.y);
            u.z = cvt_tf32(v.z); u.w = cvt_tf32(v.w);
            *(uint4*)&As[cur][(ar + 32 * p) * 20 + ac] = u;
        }
        *(float4*)&Bs[cur][(ar     ) * 20 + ac] = bR[0];
        *(float4*)&Bs[cur][(ar + 32) * 20 + ac] = bR[1];
        __syncthreads();

        if (kk + 16 < DDIM) {   // prefetch next chunk (hidden under mma)
            #pragma unroll
            for (int p = 0; p < 4; ++p)
                aR[p] = *(const float4*)(aG + (size_t)(32 * p) * DDIM + kk + 16);
            bR[0] = *(const float4*)(bG + kk + 16);
            bR[1] = *(const float4*)(bG + (size_t)32 * DDIM + kk + 16);
        }

        #pragma unroll
        for (int ks = 0; ks < 2; ++ks) {
            const int kb = ks * 8;
            unsigned a[2][4];
            #pragma unroll
            for (int i = 0; i < 2; ++i) {
                const int mr = 32 * warp + 16 * i;
                a[i][0] = __float_as_uint(As[cur][(mr + g    ) * 20 + kb + tid    ]);
                a[i][1] = __float_as_uint(As[cur][(mr + 8 + g) * 20 + kb + tid    ]);
                a[i][2] = __float_as_uint(As[cur][(mr + g    ) * 20 + kb + tid + 4]);
                a[i][3] = __float_as_uint(As[cur][(mr + 8 + g) * 20 + kb + tid + 4]);
            }
            #pragma unroll
            for (int j = 0; j < 8; ++j) {
                const unsigned b0 = __float_as_uint(Bs[cur][(8*j + g) * 20 + kb + tid    ]);
                const unsigned b1 = __float_as_uint(Bs[cur][(8*j + g) * 20 + kb + tid + 4]);
                mma_tf32(acc[0][j], a[0], b0, b1);
                mma_tf32(acc[1][j], a[1], b0, b1);
            }
        }
        __syncthreads();
    }

    // per-row 1/||fX||: each row's ssq split across 4 loader threads (ac groups)
    #pragma unroll
    for (int p = 0; p < 4; ++p) s_pn[p][ar][t & 3] = ssq[p];
    __syncthreads();
    {
        const int m = t;  // 0..127
        const float s = s_pn[m >> 5][m & 31][0] + s_pn[m >> 5][m & 31][1]
                      + s_pn[m >> 5][m & 31][2] + s_pn[m >> 5][m & 31][3];
        s_finv[m] = rsqrtf(s);
    }
    __syncthreads();

    // epilogue: D layout d0=(g,2tid) d1=(g,2tid+1) d2=(g+8,2tid) d3=(g+8,2tid+1)
    #pragma unroll
    for (int i = 0; i < 2; ++i) {
        const int mr = 32 * warp + 16 * i;
        const int r0 = mr + g, r1 = mr + 8 + g;
        const float f0 = s_finv[r0], f1 = s_finv[r1];
        #pragma unroll
        for (int j = 0; j < 8; ++j) {
            const int col = 8 * j + 2 * tid;
            float2 o0, o1;
            o0.x = acc[i][j][0] * f0;  o0.y = acc[i][j][1] * f0;
            o1.x = acc[i][j][2] * f1;  o1.y = acc[i][j][3] * f1;
            *(float2*)&out[(size_t)(m0 + r0) * NCLS + col] = o0;
            *(float2*)&out[(size_t)(m0 + r1) * NCLS + col] = o1;
        }
    }
}

// ---------------------------------------------------------------------------
// inputs: gS [N,1024] f32, fX [M,1024] f32, trainTarget [N] i64/i32, nClasses
// output: [M, 64] f32
// ---------------------------------------------------------------------------
extern "C" void kernel_launch(void* const* d_in, const int* in_sizes, int n_in,
                              void* d_out, int out_size) {
    const float* gS = (const float*)d_in[0];
    const float* fX = (const float*)d_in[1];
    const void*  tg = d_in[2];

    const int N = in_sizes[0] / DDIM;   // 4096
    const int M = in_sizes[1] / DDIM;   // 8192

    norms_kernel<<<N / 8, 256>>>(gS);
    build_kernel<<<NCLS, 256>>>(tg, N);
    gather_kernel<<<NCLS * 8, 128>>>(gS);
    gemm_kernel<<<M / 128, 128>>>(fX, (float*)d_out);
}

// round 4
// speedup vs baseline: 1.5015x; 1.2353x over previous
#include <cuda_runtime.h>
#include <math.h>

#define DDIM 1024
#define NCLS 64
#define NSUP 4096
#define RCAP 192

// Scratch (device globals — no allocation allowed)
__device__ float g_W[NCLS * DDIM];     // class-aggregated normalized supports (tf32-rounded)
__device__ float g_rinv[NSUP];         // 1/||gS[n]||
__device__ int   g_rows[NCLS * RCAP];  // ordered row lists per class
__device__ int   g_cnt[NCLS];

__device__ __forceinline__ unsigned cvt_tf32(float f) {
    unsigned u;
    asm("cvt.rna.tf32.f32 %0, %1;" : "=r"(u) : "f"(f));
    return u;
}

__device__ __forceinline__ void mma_tf32(float* d, const unsigned* a,
                                         unsigned b0, unsigned b1) {
    asm volatile(
        "mma.sync.aligned.m16n8k8.row.col.f32.tf32.tf32.f32 "
        "{%0,%1,%2,%3}, {%4,%5,%6,%7}, {%8,%9}, {%0,%1,%2,%3};"
        : "+f"(d[0]), "+f"(d[1]), "+f"(d[2]), "+f"(d[3])
        : "r"(a[0]), "r"(a[1]), "r"(a[2]), "r"(a[3]), "r"(b0), "r"(b1));
}

// ---------------------------------------------------------------------------
// Kernel 1: rinv[n] = rsqrt(||gS[n]||^2). 2 rows per warp (MLP=16), 16 rows
// per block, grid 256.
// ---------------------------------------------------------------------------
__global__ __launch_bounds__(256) void norms_kernel(const float* __restrict__ gS) {
    const int warp = threadIdx.x >> 5;
    const int lane = threadIdx.x & 31;
    const int n0 = blockIdx.x * 16 + warp * 2;

    const float4* r0 = reinterpret_cast<const float4*>(gS + (size_t)n0 * DDIM);
    const float4* r1 = reinterpret_cast<const float4*>(gS + (size_t)(n0 + 1) * DDIM);
    float s0 = 0.0f, s1 = 0.0f;
    #pragma unroll
    for (int i = 0; i < 8; ++i) {
        const float4 a = r0[lane + 32 * i];
        const float4 b = r1[lane + 32 * i];
        s0 += a.x*a.x + a.y*a.y + a.z*a.z + a.w*a.w;
        s1 += b.x*b.x + b.y*b.y + b.z*b.z + b.w*b.w;
    }
    #pragma unroll
    for (int o = 16; o > 0; o >>= 1) {
        s0 += __shfl_xor_sync(0xffffffffu, s0, o);
        s1 += __shfl_xor_sync(0xffffffffu, s1, o);
    }
    if (lane == 0) {
        g_rinv[n0]     = rsqrtf(s0);
        g_rinv[n0 + 1] = rsqrtf(s1);
    }
}

// ---------------------------------------------------------------------------
// Kernel 2: build ordered per-class row lists. One block per class; per-warp
// ballot compaction over disjoint segments, ordered concat. Deterministic.
// ---------------------------------------------------------------------------
__global__ __launch_bounds__(256) void build_kernel(const void* __restrict__ tgt_raw,
                                                    int N) {
    const int c = blockIdx.x;
    const int t = threadIdx.x;
    const int warp = t >> 5, lane = t & 31;

    __shared__ int   s_is64;
    __shared__ short s_stage[8][64];
    __shared__ int   s_wcnt[8];
    __shared__ int   s_off[9];

    const int* tgt32 = (const int*)tgt_raw;
    if (t == 0) {
        int acc = 0;
        #pragma unroll 4
        for (int i = 1; i < 128; i += 2) acc |= tgt32[i];  // int64 => odd words 0
        s_is64 = (acc == 0);
    }
    __syncthreads();
    const int is64 = s_is64;

    const int seg = N >> 3;
    const int base = warp * seg;
    int cnt = 0;
    for (int ch = 0; ch < seg; ch += 32) {
        const int n = base + ch + lane;
        const int lbl = is64 ? tgt32[2 * n] : tgt32[n];
        const bool m = (lbl == c);
        const unsigned msk = __ballot_sync(0xffffffffu, m);
        if (m) {
            int pos = cnt + __popc(msk & ((1u << lane) - 1u));
            if (pos < 64) s_stage[warp][pos] = (short)n;
        }
        cnt += __popc(msk);
    }
    if (cnt > 64) cnt = 64;
    if (lane == 0) s_wcnt[warp] = cnt;
    __syncthreads();
    if (t == 0) {
        int o = 0;
        #pragma unroll
        for (int w = 0; w < 8; ++w) { s_off[w] = o; o += s_wcnt[w]; }
        s_off[8] = o;
        g_cnt[c] = (o < RCAP) ? o : RCAP;
    }
    __syncthreads();
    for (int i = lane; i < s_wcnt[warp]; i += 32) {
        const int pos = s_off[warp] + i;
        if (pos < RCAP) g_rows[c * RCAP + pos] = (int)s_stage[warp][i];
    }
}

// ---------------------------------------------------------------------------
// Kernel 3: gather. Block (c, 128-d slice) sums gS[n][d]*rinv[n] over the
// ordered row list (deterministic; gS L2-resident). Output tf32-rounded.
// ---------------------------------------------------------------------------
__global__ __launch_bounds__(128) void gather_kernel(const float* __restrict__ gS) {
    const int c  = blockIdx.x >> 3;
    const int sl = blockIdx.x & 7;
    const int t  = threadIdx.x;

    const int cnt = g_cnt[c];
    const int* rows = g_rows + c * RCAP;
    const float* gsl = gS + sl * 128 + t;

    float a0 = 0.f, a1 = 0.f, a2 = 0.f, a3 = 0.f;
    int r = 0;
    for (; r + 4 <= cnt; r += 4) {
        const int n0 = rows[r], n1 = rows[r+1], n2 = rows[r+2], n3 = rows[r+3];
        a0 += gsl[(size_t)n0 * DDIM] * g_rinv[n0];
        a1 += gsl[(size_t)n1 * DDIM] * g_rinv[n1];
        a2 += gsl[(size_t)n2 * DDIM] * g_rinv[n2];
        a3 += gsl[(size_t)n3 * DDIM] * g_rinv[n3];
    }
    for (; r < cnt; ++r) {
        const int n0 = rows[r];
        a0 += gsl[(size_t)n0 * DDIM] * g_rinv[n0];
    }
    const float v = (a0 + a1) + (a2 + a3);
    g_W[c * DDIM + sl * 128 + t] = __uint_as_float(cvt_tf32(v));
}

// ---------------------------------------------------------------------------
// Kernel 4: tensor GEMM. out[m][c] = (fX[m].W[c]) * rsqrt(||fX[m]||^2)
// Block 64m x 64c, 256 threads (8 warps), grid 128.
// Warp tile 32m x 32c; k-split-2: warp w and w+4 take opposite 16-k halves
// of each 32-k chunk; partials merged via smem at epilogue.
// Double-buffered smem, row stride 36 (conflict-free for all patterns).
// fX read exactly once; ssq fused on the load path (f32), A tf32-rounded on
// the smem-store path; B pre-rounded by gather.
// ---------------------------------------------------------------------------
#define PAD 36
__global__ __launch_bounds__(256) void gemm_kernel(
    const float* __restrict__ fX, float* __restrict__ out) {

    __shared__ __align__(16) float As[2 * 64 * PAD];
    __shared__ __align__(16) float Bs[2 * 64 * PAD];
    __shared__ float s_pn[64][4];
    __shared__ float s_finv[64];

    const int t    = threadIdx.x;
    const int w    = t >> 5;
    const int lane = t & 31;
    const int g    = lane >> 2;
    const int tid  = lane & 3;
    const int m0   = blockIdx.x * 64;

    const int kw = w >> 2;        // k-half 0/1
    const int wp = w & 3;
    const int mq = wp >> 1;       // m offset 32*mq
    const int cq = wp & 1;        // c offset 32*cq

    // loader mapping: row r (0..63), quad q -> cols q*4 and q*4+16
    const int r = t >> 2;
    const int q = t & 3;
    const int c0 = q * 4;

    const float* aG = fX  + (size_t)(m0 + r) * DDIM + c0;
    const float* bG = g_W + (size_t)r        * DDIM + c0;

    float acc[2][4][4];
    #pragma unroll
    for (int i = 0; i < 2; ++i)
        #pragma unroll
        for (int j = 0; j < 4; ++j)
            #pragma unroll
            for (int k = 0; k < 4; ++k) acc[i][j][k] = 0.0f;

    float ssq = 0.0f;

    float4 aR0 = *(const float4*)(aG);
    float4 aR1 = *(const float4*)(aG + 16);
    float4 bR0 = *(const float4*)(bG);
    float4 bR1 = *(const float4*)(bG + 16);

    const int kb0 = 16 * kw;

    for (int kk = 0; kk < DDIM; kk += 32) {
        const int cur = (kk >> 5) & 1;
        float* a_s = As + cur * 64 * PAD;
        float* b_s = Bs + cur * 64 * PAD;

        // commit prefetched chunk (ssq in f32, A rounded to tf32)
        {
            ssq += aR0.x*aR0.x + aR0.y*aR0.y + aR0.z*aR0.z + aR0.w*aR0.w
                 + aR1.x*aR1.x + aR1.y*aR1.y + aR1.z*aR1.z + aR1.w*aR1.w;
            uint4 u0, u1;
            u0.x = cvt_tf32(aR0.x); u0.y = cvt_tf32(aR0.y);
            u0.z = cvt_tf32(aR0.z); u0.w = cvt_tf32(aR0.w);
            u1.x = cvt_tf32(aR1.x); u1.y = cvt_tf32(aR1.y);
            u1.z = cvt_tf32(aR1.z); u1.w = cvt_tf32(aR1.w);
            *(uint4*)&a_s[r * PAD + c0     ] = u0;
            *(uint4*)&a_s[r * PAD + c0 + 16] = u1;
            *(float4*)&b_s[r * PAD + c0     ] = bR0;
            *(float4*)&b_s[r * PAD + c0 + 16] = bR1;
        }
        __syncthreads();

        if (kk + 32 < DDIM) {   // prefetch next chunk, hidden under mma
            aR0 = *(const float4*)(aG + kk + 32);
            aR1 = *(const float4*)(aG + kk + 48);
            bR0 = *(const float4*)(bG + kk + 32);
            bR1 = *(const float4*)(bG + kk + 48);
        }

        #pragma unroll
        for (int ks = 0; ks < 2; ++ks) {
            const int kb = kb0 + 8 * ks;
            unsigned a[2][4];
            #pragma unroll
            for (int i = 0; i < 2; ++i) {
                const int mr = 32 * mq + 16 * i;
                a[i][0] = __float_as_uint(a_s[(mr + g    ) * PAD + kb + tid    ]);
                a[i][1] = __float_as_uint(a_s[(mr + 8 + g) * PAD + kb + tid    ]);
                a[i][2] = __float_as_uint(a_s[(mr + g    ) * PAD + kb + tid + 4]);
                a[i][3] = __float_as_uint(a_s[(mr + 8 + g) * PAD + kb + tid + 4]);
            }
            #pragma unroll
            for (int j = 0; j < 4; ++j) {
                const int cr = 32 * cq + 8 * j + g;
                const unsigned b0 = __float_as_uint(b_s[cr * PAD + kb + tid    ]);
                const unsigned b1 = __float_as_uint(b_s[cr * PAD + kb + tid + 4]);
                mma_tf32(acc[0][j], a[0], b0, b1);
                mma_tf32(acc[1][j], a[1], b0, b1);
            }
        }
        __syncthreads();
    }

    // ---- epilogue ----
    s_pn[r][q] = ssq;

    // k-split merge: high warps dump accs into (reused) As, pad 33
    float* epi = As;
    if (kw == 1) {
        const int base = (wp * 32 + lane) * 33;
        #pragma unroll
        for (int i = 0; i < 2; ++i)
            #pragma unroll
            for (int j = 0; j < 4; ++j)
                #pragma unroll
                for (int k = 0; k < 4; ++k)
                    epi[base + i * 16 + j * 4 + k] = acc[i][j][k];
    }
    __syncthreads();

    if (t < 64) {
        const float s = s_pn[t][0] + s_pn[t][1] + s_pn[t][2] + s_pn[t][3];
        s_finv[t] = rsqrtf(s);
    }
    __syncthreads();

    if (kw == 0) {
        const int base = (wp * 32 + lane) * 33;
        #pragma unroll
        for (int i = 0; i < 2; ++i) {
            const int r0 = 32 * mq + 16 * i + g;
            const int r1 = r0 + 8;
            const float f0 = s_finv[r0], f1 = s_finv[r1];
            #pragma unroll
            for (int j = 0; j < 4; ++j) {
                const int col = 32 * cq + 8 * j + 2 * tid;
                float2 o0, o1;
                o0.x = (acc[i][j][0] + epi[base + i*16 + j*4 + 0]) * f0;
                o0.y = (acc[i][j][1] + epi[base + i*16 + j*4 + 1]) * f0;
                o1.x = (acc[i][j][2] + epi[base + i*16 + j*4 + 2]) * f1;
                o1.y = (acc[i][j][3] + epi[base + i*16 + j*4 + 3]) * f1;
                *(float2*)&out[(size_t)(m0 + r0) * NCLS + col] = o0;
                *(float2*)&out[(size_t)(m0 + r1) * NCLS + col] = o1;
            }
        }
    }
}

// ---------------------------------------------------------------------------
// inputs: gS [N,1024] f32, fX [M,1024] f32, trainTarget [N] i64/i32, nClasses
// output: [M, 64] f32
// ---------------------------------------------------------------------------
extern "C" void kernel_launch(void* const* d_in, const int* in_sizes, int n_in,
                              void* d_out, int out_size) {
    const float* gS = (const float*)d_in[0];
    const float* fX = (const float*)d_in[1];
    const void*  tg = d_in[2];

    const int N = in_sizes[0] / DDIM;   // 4096
    const int M = in_sizes[1] / DDIM;   // 8192

    norms_kernel<<<N / 16, 256>>>(gS);
    build_kernel<<<NCLS, 256>>>(tg, N);
    gather_kernel<<<NCLS * 8, 128>>>(gS);
    gemm_kernel<<<M / 64, 256>>>(fX, (float*)d_out);
}